// round 3
// baseline (speedup 1.0000x reference)
#include <cuda_runtime.h>
#include <cuda_bf16.h>
#include <cstdint>

// Problem constants (fixed by the reference)
#define F 26
#define D 128
#define NROWS 100000
#define B 4096
#define T (B * 20)

// One warp per (feature, bag). Lane l owns float4 chunk l of the 128-float row.
// D = 128 floats = 32 float4 -> exactly one float4 per lane, one fully
// coalesced 512B row read per gathered index.
// NOTE: indices/offsets are int32 on device (JAX x64 disabled downcasts int64).
__global__ __launch_bounds__(256) void ebag_pool_kernel(
    const float* __restrict__ tables,   // [F, NROWS, D]
    const int* __restrict__ values,     // [F, T]
    const int* __restrict__ offsets,    // [F, B+1]
    float* __restrict__ out)            // [B, F, D]
{
    const int lane = threadIdx.x & 31;
    const int warp = threadIdx.x >> 5;
    const int bag  = blockIdx.x * 8 + warp;     // 8 warps per block
    const int f    = blockIdx.y;
    if (bag >= B) return;

    const int* offs = offsets + (size_t)f * (B + 1);
    const int s = __ldg(offs + bag);
    const int e = __ldg(offs + bag + 1);

    const int* vals = values + (size_t)f * T;
    const float4* tab = reinterpret_cast<const float4*>(
        tables + (size_t)f * NROWS * D);

    float4 a0 = make_float4(0.f, 0.f, 0.f, 0.f);
    float4 a1 = make_float4(0.f, 0.f, 0.f, 0.f);
    float4 a2 = make_float4(0.f, 0.f, 0.f, 0.f);
    float4 a3 = make_float4(0.f, 0.f, 0.f, 0.f);

    int i = s;
    // Unroll x4 with independent accumulators -> MLP >= 4 on the gathers.
    for (; i + 4 <= e; i += 4) {
        int i0 = __ldg(vals + i + 0);
        int i1 = __ldg(vals + i + 1);
        int i2 = __ldg(vals + i + 2);
        int i3 = __ldg(vals + i + 3);
        float4 v0 = __ldg(tab + (size_t)i0 * 32 + lane);
        float4 v1 = __ldg(tab + (size_t)i1 * 32 + lane);
        float4 v2 = __ldg(tab + (size_t)i2 * 32 + lane);
        float4 v3 = __ldg(tab + (size_t)i3 * 32 + lane);
        a0.x += v0.x; a0.y += v0.y; a0.z += v0.z; a0.w += v0.w;
        a1.x += v1.x; a1.y += v1.y; a1.z += v1.z; a1.w += v1.w;
        a2.x += v2.x; a2.y += v2.y; a2.z += v2.z; a2.w += v2.w;
        a3.x += v3.x; a3.y += v3.y; a3.z += v3.z; a3.w += v3.w;
    }
    for (; i < e; ++i) {
        int i0 = __ldg(vals + i);
        float4 v0 = __ldg(tab + (size_t)i0 * 32 + lane);
        a0.x += v0.x; a0.y += v0.y; a0.z += v0.z; a0.w += v0.w;
    }

    float4 acc;
    acc.x = (a0.x + a1.x) + (a2.x + a3.x);
    acc.y = (a0.y + a1.y) + (a2.y + a3.y);
    acc.z = (a0.z + a1.z) + (a2.z + a3.z);
    acc.w = (a0.w + a1.w) + (a2.w + a3.w);

    // out[b][f][:] — always write (d_out is poisoned; empty bags must be 0)
    float4* o = reinterpret_cast<float4*>(out) + ((size_t)bag * F + f) * 32;
    o[lane] = acc;
}

extern "C" void kernel_launch(void* const* d_in, const int* in_sizes, int n_in,
                              void* d_out, int out_size) {
    const float* tables   = (const float*)d_in[0];
    const int*   values   = (const int*)d_in[1];
    const int*   offsets  = (const int*)d_in[2];
    float* out = (float*)d_out;

    dim3 grid(B / 8, F);   // feature on y: consecutive blocks share one table (L2 reuse)
    dim3 block(256);       // 8 warps = 8 bags per block
    ebag_pool_kernel<<<grid, block>>>(tables, values, offsets, out);
}

// round 4
// speedup vs baseline: 1.0002x; 1.0002x over previous
#include <cuda_runtime.h>
#include <cuda_bf16.h>
#include <cstdint>

// Problem constants (fixed by the reference)
#define F 26
#define D 128
#define NROWS 100000
#define B 4096
#define T (B * 20)

// One warp per (feature, bag). Lane l owns float4 chunk l of the 128-float row.
// D = 128 floats = 32 float4 -> exactly one float4 per lane, one fully
// coalesced 512B row read per gathered index.
// NOTE: indices/offsets are int32 on device (JAX x64 disabled downcasts int64).
__global__ __launch_bounds__(256) void ebag_pool_kernel(
    const float* __restrict__ tables,   // [F, NROWS, D]
    const int* __restrict__ values,     // [F, T]
    const int* __restrict__ offsets,    // [F, B+1]
    float* __restrict__ out)            // [B, F, D]
{
    const int lane = threadIdx.x & 31;
    const int warp = threadIdx.x >> 5;
    const int bag  = blockIdx.x * 8 + warp;     // 8 warps per block
    const int f    = blockIdx.y;
    if (bag >= B) return;

    const int* offs = offsets + (size_t)f * (B + 1);
    const int s = __ldg(offs + bag);
    const int e = __ldg(offs + bag + 1);

    const int* vals = values + (size_t)f * T;
    const float4* tab = reinterpret_cast<const float4*>(
        tables + (size_t)f * NROWS * D);

    float4 a0 = make_float4(0.f, 0.f, 0.f, 0.f);
    float4 a1 = make_float4(0.f, 0.f, 0.f, 0.f);
    float4 a2 = make_float4(0.f, 0.f, 0.f, 0.f);
    float4 a3 = make_float4(0.f, 0.f, 0.f, 0.f);

    int i = s;
    // Unroll x4 with independent accumulators -> MLP >= 4 on the gathers.
    for (; i + 4 <= e; i += 4) {
        int i0 = __ldg(vals + i + 0);
        int i1 = __ldg(vals + i + 1);
        int i2 = __ldg(vals + i + 2);
        int i3 = __ldg(vals + i + 3);
        float4 v0 = __ldg(tab + (size_t)i0 * 32 + lane);
        float4 v1 = __ldg(tab + (size_t)i1 * 32 + lane);
        float4 v2 = __ldg(tab + (size_t)i2 * 32 + lane);
        float4 v3 = __ldg(tab + (size_t)i3 * 32 + lane);
        a0.x += v0.x; a0.y += v0.y; a0.z += v0.z; a0.w += v0.w;
        a1.x += v1.x; a1.y += v1.y; a1.z += v1.z; a1.w += v1.w;
        a2.x += v2.x; a2.y += v2.y; a2.z += v2.z; a2.w += v2.w;
        a3.x += v3.x; a3.y += v3.y; a3.z += v3.z; a3.w += v3.w;
    }
    for (; i < e; ++i) {
        int i0 = __ldg(vals + i);
        float4 v0 = __ldg(tab + (size_t)i0 * 32 + lane);
        a0.x += v0.x; a0.y += v0.y; a0.z += v0.z; a0.w += v0.w;
    }

    float4 acc;
    acc.x = (a0.x + a1.x) + (a2.x + a3.x);
    acc.y = (a0.y + a1.y) + (a2.y + a3.y);
    acc.z = (a0.z + a1.z) + (a2.z + a3.z);
    acc.w = (a0.w + a1.w) + (a2.w + a3.w);

    // out[b][f][:] — always write (d_out is poisoned; empty bags must be 0)
    float4* o = reinterpret_cast<float4*>(out) + ((size_t)bag * F + f) * 32;
    o[lane] = acc;
}

extern "C" void kernel_launch(void* const* d_in, const int* in_sizes, int n_in,
                              void* d_out, int out_size) {
    const float* tables   = (const float*)d_in[0];
    const int*   values   = (const int*)d_in[1];
    const int*   offsets  = (const int*)d_in[2];
    float* out = (float*)d_out;

    dim3 grid(B / 8, F);   // feature on y: consecutive blocks share one table (L2 reuse)
    dim3 block(256);       // 8 warps = 8 bags per block
    ebag_pool_kernel<<<grid, block>>>(tables, values, offsets, out);
}

// round 5
// speedup vs baseline: 1.0566x; 1.0564x over previous
#include <cuda_runtime.h>
#include <cuda_bf16.h>
#include <cstdint>

#define F 26
#define D 128
#define NROWS 100000
#define B 4096
#define T (B * 20)

// Warp per (feature, bag). Lane l owns float4 chunk l of the 128-float row.
// Indices fetched warp-cooperatively (1 coalesced LDG per 32 indices) and
// broadcast via shfl; row gathers unrolled x8 for deep MLP.
__global__ __launch_bounds__(128) void ebag_pool_kernel(
    const float* __restrict__ tables,   // [F, NROWS, D]
    const int* __restrict__ values,     // [F, T]
    const int* __restrict__ offsets,    // [F, B+1]
    float* __restrict__ out)            // [B, F, D]
{
    const int lane = threadIdx.x & 31;
    const int warp = threadIdx.x >> 5;
    const int bag  = blockIdx.x * 4 + warp;     // 4 warps per block
    const int f    = blockIdx.y;

    const int* offs = offsets + (size_t)f * (B + 1);
    const int s = __ldg(offs + bag);
    const int e = __ldg(offs + bag + 1);

    const int* vals = values + (size_t)f * T;
    const float4* tab = reinterpret_cast<const float4*>(
        tables + (size_t)f * NROWS * D);

    float4 a0 = make_float4(0.f, 0.f, 0.f, 0.f);
    float4 a1 = make_float4(0.f, 0.f, 0.f, 0.f);
    float4 a2 = make_float4(0.f, 0.f, 0.f, 0.f);
    float4 a3 = make_float4(0.f, 0.f, 0.f, 0.f);

    for (int base = s; base < e; base += 32) {
        const int n = min(32, e - base);
        // One coalesced index load per warp covers 32 bag entries.
        int myidx = 0;
        if (base + lane < e) myidx = __ldg(vals + base + lane);

        int j = 0;
        // x8 unroll: 8 independent row gathers in flight per warp.
        for (; j + 8 <= n; j += 8) {
            int r0 = __shfl_sync(0xffffffffu, myidx, j + 0);
            int r1 = __shfl_sync(0xffffffffu, myidx, j + 1);
            int r2 = __shfl_sync(0xffffffffu, myidx, j + 2);
            int r3 = __shfl_sync(0xffffffffu, myidx, j + 3);
            int r4 = __shfl_sync(0xffffffffu, myidx, j + 4);
            int r5 = __shfl_sync(0xffffffffu, myidx, j + 5);
            int r6 = __shfl_sync(0xffffffffu, myidx, j + 6);
            int r7 = __shfl_sync(0xffffffffu, myidx, j + 7);
            float4 v0 = __ldg(tab + (size_t)r0 * 32 + lane);
            float4 v1 = __ldg(tab + (size_t)r1 * 32 + lane);
            float4 v2 = __ldg(tab + (size_t)r2 * 32 + lane);
            float4 v3 = __ldg(tab + (size_t)r3 * 32 + lane);
            float4 v4 = __ldg(tab + (size_t)r4 * 32 + lane);
            float4 v5 = __ldg(tab + (size_t)r5 * 32 + lane);
            float4 v6 = __ldg(tab + (size_t)r6 * 32 + lane);
            float4 v7 = __ldg(tab + (size_t)r7 * 32 + lane);
            a0.x += v0.x; a0.y += v0.y; a0.z += v0.z; a0.w += v0.w;
            a1.x += v1.x; a1.y += v1.y; a1.z += v1.z; a1.w += v1.w;
            a2.x += v2.x; a2.y += v2.y; a2.z += v2.z; a2.w += v2.w;
            a3.x += v3.x; a3.y += v3.y; a3.z += v3.z; a3.w += v3.w;
            a0.x += v4.x; a0.y += v4.y; a0.z += v4.z; a0.w += v4.w;
            a1.x += v5.x; a1.y += v5.y; a1.z += v5.z; a1.w += v5.w;
            a2.x += v6.x; a2.y += v6.y; a2.z += v6.z; a2.w += v6.w;
            a3.x += v7.x; a3.y += v7.y; a3.z += v7.z; a3.w += v7.w;
        }
        for (; j + 4 <= n; j += 4) {
            int r0 = __shfl_sync(0xffffffffu, myidx, j + 0);
            int r1 = __shfl_sync(0xffffffffu, myidx, j + 1);
            int r2 = __shfl_sync(0xffffffffu, myidx, j + 2);
            int r3 = __shfl_sync(0xffffffffu, myidx, j + 3);
            float4 v0 = __ldg(tab + (size_t)r0 * 32 + lane);
            float4 v1 = __ldg(tab + (size_t)r1 * 32 + lane);
            float4 v2 = __ldg(tab + (size_t)r2 * 32 + lane);
            float4 v3 = __ldg(tab + (size_t)r3 * 32 + lane);
            a0.x += v0.x; a0.y += v0.y; a0.z += v0.z; a0.w += v0.w;
            a1.x += v1.x; a1.y += v1.y; a1.z += v1.z; a1.w += v1.w;
            a2.x += v2.x; a2.y += v2.y; a2.z += v2.z; a2.w += v2.w;
            a3.x += v3.x; a3.y += v3.y; a3.z += v3.z; a3.w += v3.w;
        }
        for (; j < n; ++j) {
            int r0 = __shfl_sync(0xffffffffu, myidx, j);
            float4 v0 = __ldg(tab + (size_t)r0 * 32 + lane);
            a0.x += v0.x; a0.y += v0.y; a0.z += v0.z; a0.w += v0.w;
        }
    }

    float4 acc;
    acc.x = (a0.x + a1.x) + (a2.x + a3.x);
    acc.y = (a0.y + a1.y) + (a2.y + a3.y);
    acc.z = (a0.z + a1.z) + (a2.z + a3.z);
    acc.w = (a0.w + a1.w) + (a2.w + a3.w);

    float4* o = reinterpret_cast<float4*>(out) + ((size_t)bag * F + f) * 32;
    o[lane] = acc;
}

extern "C" void kernel_launch(void* const* d_in, const int* in_sizes, int n_in,
                              void* d_out, int out_size) {
    const float* tables  = (const float*)d_in[0];
    const int*   values  = (const int*)d_in[1];
    const int*   offsets = (const int*)d_in[2];
    float* out = (float*)d_out;

    dim3 grid(B / 4, F);   // feature on y: blocks of one feature grouped -> L2 reuse
    dim3 block(128);       // 4 warps = 4 bags per block (finer retire granularity)
    ebag_pool_kernel<<<grid, block>>>(tables, values, offsets, out);
}

// round 6
// speedup vs baseline: 1.3846x; 1.3104x over previous
#include <cuda_runtime.h>
#include <cuda_bf16.h>
#include <cstdint>

#define F 26
#define D 128
#define NROWS 100000
#define B 4096
#define T (B * 20)

// Warp per (feature, bag). Lane l owns the l-th float4 (16B) of each 512B row.
// Row gathers go global->shared via cp.async (LDGSTS): in-flight data lives in
// smem, not registers, so occupancy is high AND MLP is deep.
// Pipeline: stages of 4 rows, double-buffered (8-row ring per warp = 4KB smem).
// Each lane copies and later reads ONLY its own 16B slot -> no intra-warp sync.
__global__ __launch_bounds__(128, 12) void ebag_pool_kernel(
    const float* __restrict__ tables,   // [F, NROWS, D]
    const int* __restrict__ values,     // [F, T]
    const int* __restrict__ offsets,    // [F, B+1]
    float* __restrict__ out)            // [B, F, D]
{
    __shared__ float4 buf[4][8][32];    // [warp][row-slot][lane]  = 16KB

    const int lane = threadIdx.x & 31;
    const int warp = threadIdx.x >> 5;
    const int bag  = blockIdx.x * 4 + warp;
    const int f    = blockIdx.y;

    const int* offs = offsets + f * (B + 1);
    const int s = __ldg(offs + bag);
    const int e = __ldg(offs + bag + 1);

    const int* vals = values + (size_t)f * T;
    const char* tabb = reinterpret_cast<const char*>(
        tables + (size_t)f * NROWS * D);

    // byte address in shared space of buf[warp][0][lane]; slot k is +k*512B
    uint32_t sb0 = (uint32_t)__cvta_generic_to_shared(&buf[warp][0][lane]);

    float4 a0 = make_float4(0.f, 0.f, 0.f, 0.f);
    float4 a1 = make_float4(0.f, 0.f, 0.f, 0.f);

    for (int base = s; base < e; base += 32) {
        const int n = min(32, e - base);
        // One coalesced index load covers up to 32 bag entries.
        int myidx = 0;
        if (base + lane < e) myidx = __ldg(vals + base + lane);

        const int nstage = (n + 3) >> 2;
        int sbuf = 0;       // which half of the 8-slot ring we are filling
        int prevcnt = 0;    // valid rows in the previously issued stage

        for (int st = 0; st < nstage; ++st) {
            const int cnt = min(4, n - st * 4);
            // Issue this stage's rows (each lane copies its own 16B of the row).
            #pragma unroll
            for (int q = 0; q < 4; ++q) {
                if (q < cnt) {
                    int r = __shfl_sync(0xffffffffu, myidx, st * 4 + q);
                    const char* src = tabb + ((size_t)(unsigned)r << 9) + (lane << 4);
                    uint32_t dst = sb0 + (uint32_t)((sbuf * 4 + q) << 9);
                    asm volatile("cp.async.cg.shared.global [%0], [%1], 16;\n"
                                 :: "r"(dst), "l"(src));
                }
            }
            asm volatile("cp.async.commit_group;\n");

            // Accumulate the previous stage while this one is in flight.
            if (st > 0) {
                asm volatile("cp.async.wait_group 1;\n");
                const int pb = (sbuf ^ 1) * 4;
                #pragma unroll
                for (int q = 0; q < 4; ++q) {
                    if (q < prevcnt) {
                        float4 v = buf[warp][pb + q][lane];
                        if (q & 1) { a1.x += v.x; a1.y += v.y; a1.z += v.z; a1.w += v.w; }
                        else       { a0.x += v.x; a0.y += v.y; a0.z += v.z; a0.w += v.w; }
                    }
                }
            }
            prevcnt = cnt;
            sbuf ^= 1;
        }

        // Drain the last stage of this chunk.
        if (nstage > 0) {
            asm volatile("cp.async.wait_group 0;\n");
            const int pb = (sbuf ^ 1) * 4;
            #pragma unroll
            for (int q = 0; q < 4; ++q) {
                if (q < prevcnt) {
                    float4 v = buf[warp][pb + q][lane];
                    if (q & 1) { a1.x += v.x; a1.y += v.y; a1.z += v.z; a1.w += v.w; }
                    else       { a0.x += v.x; a0.y += v.y; a0.z += v.z; a0.w += v.w; }
                }
            }
        }
    }

    float4 acc;
    acc.x = a0.x + a1.x;
    acc.y = a0.y + a1.y;
    acc.z = a0.z + a1.z;
    acc.w = a0.w + a1.w;

    // out[b][f][:] — always write (empty bags must be 0; d_out is poisoned)
    float4* o = reinterpret_cast<float4*>(out) + ((size_t)bag * F + f) * 32;
    o[lane] = acc;
}

extern "C" void kernel_launch(void* const* d_in, const int* in_sizes, int n_in,
                              void* d_out, int out_size) {
    const float* tables  = (const float*)d_in[0];
    const int*   values  = (const int*)d_in[1];
    const int*   offsets = (const int*)d_in[2];
    float* out = (float*)d_out;

    dim3 grid(B / 4, F);   // feature on y: blocks of one feature grouped -> L2 reuse
    dim3 block(128);       // 4 warps = 4 bags per block
    ebag_pool_kernel<<<grid, block>>>(tables, values, offsets, out);
}